// round 1
// baseline (speedup 1.0000x reference)
#include <cuda_runtime.h>

#define BTn 32768
#define Tn  256
#define Cn  384
#define Hn  6
#define Vn  65
#define Fn  1536

// ---- scratch (device globals: allocation-free rule) ----
__device__ float g_x[BTn * Cn];        // embeddings
__device__ float g_qkvw[Cn * 72];      // packed qkv weight [C, 72]
__device__ float g_qkv[BTn * 72];      // q|k|v per token
__device__ float g_attn[BTn * 24];     // attention output (head-interleaved)
__device__ float g_x2[BTn * Cn];       // after proj
__device__ float g_h[BTn * Fn];        // FFN hidden
__device__ float g_x3[BTn * Cn];       // after FFN
__device__ float g_rowloss[BTn];       // per-row NLL

// ---------------------------------------------------------------------------
// Pack Wq/Wk/Wv [H,C,D] into B-matrix layout [C, 72] with n = g*24 + h*4 + d
// ---------------------------------------------------------------------------
__global__ void pack_qkvw_kernel(const float* __restrict__ Wq,
                                 const float* __restrict__ Wk,
                                 const float* __restrict__ Wv) {
    int i = blockIdx.x * blockDim.x + threadIdx.x;
    if (i >= Cn * 72) return;
    int c = i / 72, n = i - c * 72;
    int g = n / 24, rem = n - g * 24;
    int h = rem >> 2, d = rem & 3;
    const float* W = (g == 0) ? Wq : (g == 1) ? Wk : Wv;
    g_qkvw[i] = W[(h * Cn + c) * 4 + d];
}

// ---------------------------------------------------------------------------
// x = tok_emb[idx] + pos_emb[t]
// ---------------------------------------------------------------------------
__global__ void embed_kernel(const int* __restrict__ idx,
                             const float* __restrict__ tok,
                             const float* __restrict__ pos) {
    int i = blockIdx.x * blockDim.x + threadIdx.x;
    if (i >= BTn * Cn) return;
    int bt = i / Cn, c = i - bt * Cn;
    int t = bt & (Tn - 1);
    g_x[i] = tok[__ldg(&idx[bt]) * Cn + c] + pos[t * Cn + c];
}

// ---------------------------------------------------------------------------
// Generic fp32 SGEMM: C[M,N] = A[M,K] @ B[K,N] (+bias, +relu)
// BM=BN=128, BK=16, 256 threads, 8x8 per thread. M must be multiple of 128.
// ---------------------------------------------------------------------------
template <bool RELU, bool HASBIAS>
__global__ __launch_bounds__(256) void gemm_kernel(
    const float* __restrict__ A, const float* __restrict__ B,
    const float* __restrict__ bias, float* __restrict__ Cmat,
    int M, int N, int K)
{
    __shared__ float As[16][132];  // padded vs 16-way bank conflict on store
    __shared__ float Bs[16][128];

    const int tid = threadIdx.x;
    const int m0 = blockIdx.y * 128;
    const int n0 = blockIdx.x * 128;
    const int tx = tid & 15;   // n-group (8 cols)
    const int ty = tid >> 4;   // m-group (8 rows)

    float acc[8][8];
#pragma unroll
    for (int i = 0; i < 8; i++)
#pragma unroll
        for (int j = 0; j < 8; j++) acc[i][j] = 0.f;

    for (int k0 = 0; k0 < K; k0 += 16) {
#pragma unroll
        for (int i = 0; i < 8; i++) {
            int idx = tid + i * 256;
            int ar = idx >> 4, ac = idx & 15;
            int gk = k0 + ac;
            float v = 0.f;
            if (gk < K) v = A[(m0 + ar) * K + gk];
            As[ac][ar] = v;
        }
#pragma unroll
        for (int i = 0; i < 8; i++) {
            int idx = tid + i * 256;
            int br = idx >> 7, bc = idx & 127;
            int gk = k0 + br, gn = n0 + bc;
            float v = 0.f;
            if (gk < K && gn < N) v = B[gk * N + gn];
            Bs[br][bc] = v;
        }
        __syncthreads();
#pragma unroll
        for (int k = 0; k < 16; k++) {
            float a[8], b[8];
            float4 t0 = *(const float4*)&As[k][ty * 8];
            float4 t1 = *(const float4*)&As[k][ty * 8 + 4];
            a[0] = t0.x; a[1] = t0.y; a[2] = t0.z; a[3] = t0.w;
            a[4] = t1.x; a[5] = t1.y; a[6] = t1.z; a[7] = t1.w;
            float4 u0 = *(const float4*)&Bs[k][tx * 8];
            float4 u1 = *(const float4*)&Bs[k][tx * 8 + 4];
            b[0] = u0.x; b[1] = u0.y; b[2] = u0.z; b[3] = u0.w;
            b[4] = u1.x; b[5] = u1.y; b[6] = u1.z; b[7] = u1.w;
#pragma unroll
            for (int i = 0; i < 8; i++)
#pragma unroll
                for (int j = 0; j < 8; j++)
                    acc[i][j] = fmaf(a[i], b[j], acc[i][j]);
        }
        __syncthreads();
    }

#pragma unroll
    for (int i = 0; i < 8; i++) {
        int gm = m0 + ty * 8 + i;
#pragma unroll
        for (int j = 0; j < 8; j++) {
            int gn = n0 + tx * 8 + j;
            if (gn < N) {
                float v = acc[i][j];
                if (HASBIAS) v += bias[gn];
                if (RELU) v = fmaxf(v, 0.f);
                Cmat[gm * N + gn] = v;
            }
        }
    }
}

// ---------------------------------------------------------------------------
// Causal attention, one block per (b,h), one thread per query row.
// d=4 -> float4; online softmax; scale = 384^-0.5 (per reference!)
// ---------------------------------------------------------------------------
__global__ __launch_bounds__(256) void attn_kernel() {
    int b = blockIdx.x / Hn;
    int h = blockIdx.x - b * Hn;
    int t = threadIdx.x;

    __shared__ float4 ks[Tn];
    __shared__ float4 vs[Tn];

    int base = (b * Tn + t) * 72;
    ks[t] = *(const float4*)&g_qkv[base + 24 + h * 4];
    vs[t] = *(const float4*)&g_qkv[base + 48 + h * 4];
    __syncthreads();

    float4 q = *(const float4*)&g_qkv[base + h * 4];
    const float scale = 0.05103103630798287f;  // 1/sqrt(384)
    q.x *= scale; q.y *= scale; q.z *= scale; q.w *= scale;

    float m = -1e30f, l = 0.f;
    float ax = 0.f, ay = 0.f, az = 0.f, aw = 0.f;
    for (int s = 0; s <= t; s++) {
        float4 k = ks[s];
        float sc = q.x * k.x + q.y * k.y + q.z * k.z + q.w * k.w;
        float mn = fmaxf(m, sc);
        float corr = __expf(m - mn);
        float p = __expf(sc - mn);
        l = l * corr + p;
        float4 v = vs[s];
        ax = ax * corr + p * v.x;
        ay = ay * corr + p * v.y;
        az = az * corr + p * v.z;
        aw = aw * corr + p * v.w;
        m = mn;
    }
    float inv = 1.f / l;
    float4 o = make_float4(ax * inv, ay * inv, az * inv, aw * inv);
    *(float4*)&g_attn[(b * Tn + t) * 24 + h * 4] = o;
}

// ---------------------------------------------------------------------------
// LM head + per-row NLL. One block (128 thr) per row; 65 logits in smem.
// Writes RAW logits to out (reference returns raw logits).
// ---------------------------------------------------------------------------
__global__ __launch_bounds__(128) void lm_kernel(const float* __restrict__ Wlm,
                                                 const float* __restrict__ blm,
                                                 const int* __restrict__ targets,
                                                 float* __restrict__ out) {
    int row = blockIdx.x;
    int tid = threadIdx.x;
    __shared__ float xs[Cn];
    __shared__ float lg[Vn];

    for (int c = tid; c < Cn; c += 128) xs[c] = g_x3[row * Cn + c];
    __syncthreads();

    if (tid < Vn) {
        float s = blm[tid];
#pragma unroll 4
        for (int c = 0; c < Cn; c++) s = fmaf(xs[c], Wlm[c * Vn + tid], s);
        lg[tid] = s;
        out[row * Vn + tid] = s;
    }
    __syncthreads();

    if (tid < 32) {
        float mx = -1e30f;
        for (int j = tid; j < Vn; j += 32) mx = fmaxf(mx, lg[j]);
#pragma unroll
        for (int o = 16; o; o >>= 1) mx = fmaxf(mx, __shfl_xor_sync(0xffffffffu, mx, o));
        float se = 0.f;
        for (int j = tid; j < Vn; j += 32) se += __expf(lg[j] - mx);
#pragma unroll
        for (int o = 16; o; o >>= 1) se += __shfl_xor_sync(0xffffffffu, se, o);
        if (tid == 0) {
            int tg = targets[row];
            g_rowloss[row] = -(lg[tg] - mx - __logf(se));
        }
    }
}

// ---------------------------------------------------------------------------
// Deterministic single-block loss reduction -> out tail (if present)
// ---------------------------------------------------------------------------
__global__ __launch_bounds__(256) void loss_reduce_kernel(float* __restrict__ out,
                                                          int out_size) {
    __shared__ float sm[256];
    int tid = threadIdx.x;
    float s = 0.f;
    for (int i = tid; i < BTn; i += 256) s += g_rowloss[i];
    sm[tid] = s;
    __syncthreads();
    for (int st = 128; st > 0; st >>= 1) {
        if (tid < st) sm[tid] += sm[tid + st];
        __syncthreads();
    }
    float loss = sm[0] * (1.f / BTn);
    for (int i = BTn * Vn + tid; i < out_size; i += 256) out[i] = loss;
}

// ---------------------------------------------------------------------------
extern "C" void kernel_launch(void* const* d_in, const int* in_sizes, int n_in,
                              void* d_out, int out_size) {
    const int*   idx     = (const int*)d_in[0];
    const int*   targets = (const int*)d_in[1];
    const float* tok     = (const float*)d_in[2];
    const float* pos     = (const float*)d_in[3];
    const float* Wq      = (const float*)d_in[4];
    const float* Wk      = (const float*)d_in[5];
    const float* Wv      = (const float*)d_in[6];
    const float* Wproj   = (const float*)d_in[7];
    const float* bproj   = (const float*)d_in[8];
    const float* W1      = (const float*)d_in[9];
    const float* b1      = (const float*)d_in[10];
    const float* W2      = (const float*)d_in[11];
    const float* b2      = (const float*)d_in[12];
    const float* Wlm     = (const float*)d_in[13];
    const float* blm     = (const float*)d_in[14];
    float* out = (float*)d_out;

    float *px, *pqkvw, *pqkv, *pattn, *px2, *ph, *px3;
    cudaGetSymbolAddress((void**)&px,    g_x);
    cudaGetSymbolAddress((void**)&pqkvw, g_qkvw);
    cudaGetSymbolAddress((void**)&pqkv,  g_qkv);
    cudaGetSymbolAddress((void**)&pattn, g_attn);
    cudaGetSymbolAddress((void**)&px2,   g_x2);
    cudaGetSymbolAddress((void**)&ph,    g_h);
    cudaGetSymbolAddress((void**)&px3,   g_x3);

    pack_qkvw_kernel<<<(Cn * 72 + 255) / 256, 256>>>(Wq, Wk, Wv);
    embed_kernel<<<(BTn * Cn + 255) / 256, 256>>>(idx, tok, pos);

    // qkv: [BT,384] @ [384,72]
    gemm_kernel<false, false><<<dim3(1, BTn / 128), 256>>>(px, pqkvw, nullptr, pqkv, BTn, 72, Cn);

    attn_kernel<<<128 * Hn, Tn>>>();

    // proj: [BT,24] @ [24,384] + bproj
    gemm_kernel<false, true><<<dim3(3, BTn / 128), 256>>>(pattn, Wproj, bproj, px2, BTn, Cn, 24);
    // ffn1: relu([BT,384] @ [384,1536] + b1)
    gemm_kernel<true, true><<<dim3(12, BTn / 128), 256>>>(px2, W1, b1, ph, BTn, Fn, Cn);
    // ffn2: [BT,1536] @ [1536,384] + b2
    gemm_kernel<false, true><<<dim3(3, BTn / 128), 256>>>(ph, W2, b2, px3, BTn, Cn, Fn);

    lm_kernel<<<BTn, 128>>>(Wlm, blm, targets, out);
    loss_reduce_kernel<<<1, 256>>>(out, out_size);
}

// round 3
// speedup vs baseline: 2.0969x; 2.0969x over previous
#include <cuda_runtime.h>
#include <cuda_bf16.h>
#include <cstdint>

#define BTn 32768
#define Tn  256
#define Cn  384
#define Hn  6
#define Vn  65
#define Fn  1536

// ---------------- scratch (device globals; allocation-free rule) -----------
__device__ __nv_bfloat16 g_xhi[BTn*Cn], g_xlo[BTn*Cn];      // embeddings split
__device__ float         g_qkvw[Cn*72];                     // packed qkv W (float)
__device__ __nv_bfloat16 g_bqkvh[128*Cn], g_bqkvl[128*Cn];  // qkv B [Npad=128,K=384]
__device__ float         g_qkv[BTn*72];                     // qkv activations
__device__ __nv_bfloat16 g_atth[BTn*64], g_attl[BTn*64];    // attn out split, padded K=64
__device__ __nv_bfloat16 g_bprojh[Cn*64], g_bprojl[Cn*64];  // proj B [384,Kpad=64]
__device__ __nv_bfloat16 g_x2h[BTn*Cn], g_x2l[BTn*Cn];      // proj out split
__device__ __nv_bfloat16 g_b1h[Fn*Cn], g_b1l[Fn*Cn];        // W1^T split [1536,384]
__device__ __nv_bfloat16 g_hh[BTn*Fn], g_hl[BTn*Fn];        // ffn hidden split
__device__ __nv_bfloat16 g_b2h[Cn*Fn], g_b2l[Cn*Fn];        // W2^T split [384,1536]
__device__ __nv_bfloat16 g_x3h[BTn*Cn], g_x3l[BTn*Cn];      // ffn out split
__device__ __nv_bfloat16 g_blmh[128*Cn], g_blml[128*Cn];    // Wlm^T split [Npad=128,384]
__device__ float         g_rowloss[BTn];

// ---------------- helpers ----------------------------------------------
__device__ __forceinline__ uint32_t smem_u32(const void* p) {
    return (uint32_t)__cvta_generic_to_shared(p);
}

__device__ __forceinline__ void cp16(uint32_t dst, const void* src) {
    asm volatile("cp.async.cg.shared.global [%0], [%1], 16;" :: "r"(dst), "l"(src));
}
#define CP_COMMIT() asm volatile("cp.async.commit_group;" ::: "memory")
#define CP_WAIT(n)  asm volatile("cp.async.wait_group %0;" :: "n"(n) : "memory")

__device__ __forceinline__ void mma_bf16(float* d, const uint32_t* a, const uint32_t* b) {
    asm volatile(
        "mma.sync.aligned.m16n8k16.row.col.f32.bf16.bf16.f32 "
        "{%0,%1,%2,%3}, {%4,%5,%6,%7}, {%8,%9}, {%0,%1,%2,%3};"
        : "+f"(d[0]), "+f"(d[1]), "+f"(d[2]), "+f"(d[3])
        : "r"(a[0]), "r"(a[1]), "r"(a[2]), "r"(a[3]), "r"(b[0]), "r"(b[1]));
}

__device__ __forceinline__ void split2(float v, __nv_bfloat16& h, __nv_bfloat16& l) {
    h = __float2bfloat16_rn(v);
    l = __float2bfloat16_rn(v - __bfloat162float(h));
}

// ---------------- small prep kernels ----------------------------------------
__global__ void pack_qkvw_kernel(const float* __restrict__ Wq,
                                 const float* __restrict__ Wk,
                                 const float* __restrict__ Wv) {
    int i = blockIdx.x * blockDim.x + threadIdx.x;
    if (i >= Cn * 72) return;
    int c = i / 72, n = i - c * 72;
    int g = n / 24, rem = n - g * 24;
    int h = rem >> 2, d = rem & 3;
    const float* W = (g == 0) ? Wq : (g == 1) ? Wk : Wv;
    g_qkvw[i] = W[(h * Cn + c) * 4 + d];
}

// split-transpose weight pack: src [K,N] row-major (ld), dst [Npad,Kpad] hi/lo
__global__ void pack_split_b(const float* __restrict__ src, int ld, int N, int Kmax,
                             int Npad, int Kpad,
                             __nv_bfloat16* __restrict__ hi, __nv_bfloat16* __restrict__ lo) {
    int i = blockIdx.x * blockDim.x + threadIdx.x;
    if (i >= Npad * Kpad) return;
    int n = i / Kpad, k = i - n * Kpad;
    float v = (n < N && k < Kmax) ? src[(size_t)k * ld + n] : 0.f;
    __nv_bfloat16 h, l; split2(v, h, l);
    hi[i] = h; lo[i] = l;
}

__global__ void embed_kernel(const int* __restrict__ idx,
                             const float* __restrict__ tok,
                             const float* __restrict__ pos) {
    int i = blockIdx.x * blockDim.x + threadIdx.x;
    if (i >= BTn * Cn) return;
    int bt = i / Cn, c = i - bt * Cn;
    int t = bt & (Tn - 1);
    float v = tok[__ldg(&idx[bt]) * Cn + c] + pos[t * Cn + c];
    __nv_bfloat16 h, l; split2(v, h, l);
    g_xhi[i] = h; g_xlo[i] = l;
}

// ---------------- mma.sync split-bf16 GEMM -----------------------------------
// C[M,N] = A[M,K] @ B^T (B stored [Npad,Kpad] K-major). 128x128 tile, BK=32.
// 256 thr = 8 warps (4M x 2N), warp tile 32x64, m16n8k16 HMMA, 3 split products.
#define BKP 40              // padded smem row length (bf16); 20 u32 -> conflict-free frags
#define TILE_B (128 * BKP * 2)   // 10240 B per operand tile
#define STAGE_B (4 * TILE_B)     // 40960 B per stage

template <bool RELU, bool HASBIAS, bool SPLITOUT>
__global__ __launch_bounds__(256) void tc_gemm(
    const __nv_bfloat16* __restrict__ Ahi, const __nv_bfloat16* __restrict__ Alo, int Kpad,
    const __nv_bfloat16* __restrict__ Bhi, const __nv_bfloat16* __restrict__ Blo,
    const float* __restrict__ bias,
    float* __restrict__ Cf, int ldc, int Nreal,
    __nv_bfloat16* __restrict__ Chi, __nv_bfloat16* __restrict__ Clo, int Npad)
{
    extern __shared__ char smem[];
    const int tid  = threadIdx.x;
    const int lane = tid & 31, wid = tid >> 5;
    const int wm = wid & 3, wn = wid >> 2;          // warp tile: rows wm*32, cols wn*64
    const int m0 = blockIdx.y * 128, n0 = blockIdx.x * 128;

    const __nv_bfloat16* gsrc[4] = {
        Ahi + (size_t)m0 * Kpad, Alo + (size_t)m0 * Kpad,
        Bhi + (size_t)n0 * Kpad, Blo + (size_t)n0 * Kpad };

    const int nk = Kpad / 32;
    const uint32_t sbase = smem_u32(smem);

    // ---- async stage loader: 4 tiles x [128 rows x 32 bf16] ----
    auto load_stage = [&](int stage, int c) {
        uint32_t dst0 = sbase + stage * STAGE_B;
        int kc0 = c * 32;
#pragma unroll
        for (int tile = 0; tile < 4; tile++) {
            const __nv_bfloat16* g = gsrc[tile] + kc0;
#pragma unroll
            for (int t = 0; t < 2; t++) {
                int j = tid + t * 256;              // 0..511
                int row = j >> 2, seg = j & 3;      // seg: 16B = 8 bf16
                cp16(dst0 + tile * TILE_B + row * (BKP * 2) + seg * 16,
                     g + (size_t)row * Kpad + seg * 8);
            }
        }
        CP_COMMIT();
    };

    float acc[2][8][4];
#pragma unroll
    for (int mi = 0; mi < 2; mi++)
#pragma unroll
        for (int nj = 0; nj < 8; nj++)
#pragma unroll
            for (int q = 0; q < 4; q++) acc[mi][nj][q] = 0.f;

    load_stage(0, 0);

    const int r8 = lane >> 2;          // 0..7
    const int q4 = lane & 3;           // 0..3

    for (int c = 0; c < nk; c++) {
        if (c + 1 < nk) { load_stage((c + 1) & 1, c + 1); CP_WAIT(1); }
        else            { CP_WAIT(0); }
        __syncthreads();

        const char* st = smem + (c & 1) * STAGE_B;
        const uint32_t* sAh = (const uint32_t*)(st);
        const uint32_t* sAl = (const uint32_t*)(st + TILE_B);
        const uint32_t* sBh = (const uint32_t*)(st + 2 * TILE_B);
        const uint32_t* sBl = (const uint32_t*)(st + 3 * TILE_B);
        const int RS = BKP / 2;        // u32 row stride (20)

#pragma unroll
        for (int step = 0; step < 2; step++) {
            const int kq = step * 8;   // u32 offset of this k16
            uint32_t ah[2][4], al[2][4];
#pragma unroll
            for (int mi = 0; mi < 2; mi++) {
                int row = wm * 32 + mi * 16 + r8;
                ah[mi][0] = sAh[row * RS + kq + q4];
                ah[mi][1] = sAh[(row + 8) * RS + kq + q4];
                ah[mi][2] = sAh[row * RS + kq + q4 + 4];
                ah[mi][3] = sAh[(row + 8) * RS + kq + q4 + 4];
                al[mi][0] = sAl[row * RS + kq + q4];
                al[mi][1] = sAl[(row + 8) * RS + kq + q4];
                al[mi][2] = sAl[row * RS + kq + q4 + 4];
                al[mi][3] = sAl[(row + 8) * RS + kq + q4 + 4];
            }
#pragma unroll
            for (int nj = 0; nj < 8; nj++) {
                int col = wn * 64 + nj * 8 + r8;
                uint32_t bh[2], bl[2];
                bh[0] = sBh[col * RS + kq + q4];
                bh[1] = sBh[col * RS + kq + q4 + 4];
                bl[0] = sBl[col * RS + kq + q4];
                bl[1] = sBl[col * RS + kq + q4 + 4];
#pragma unroll
                for (int mi = 0; mi < 2; mi++) {
                    mma_bf16(acc[mi][nj], ah[mi], bh);
                    mma_bf16(acc[mi][nj], ah[mi], bl);
                    mma_bf16(acc[mi][nj], al[mi], bh);
                }
            }
        }
        __syncthreads();
    }

    // ---- epilogue ----
#pragma unroll
    for (int mi = 0; mi < 2; mi++) {
#pragma unroll
        for (int nj = 0; nj < 8; nj++) {
            int colg = n0 + wn * 64 + nj * 8 + q4 * 2;
#pragma unroll
            for (int half = 0; half < 2; half++) {
                int rowg = m0 + wm * 32 + mi * 16 + r8 + half * 8;
                float v0 = acc[mi][nj][half * 2 + 0];
                float v1 = acc[mi][nj][half * 2 + 1];
                if (HASBIAS) { v0 += bias[colg]; v1 += bias[colg + 1]; }
                if (RELU) { v0 = fmaxf(v0, 0.f); v1 = fmaxf(v1, 0.f); }
                if (SPLITOUT) {
                    __nv_bfloat16 h0, l0, h1, l1;
                    split2(v0, h0, l0); split2(v1, h1, l1);
                    __nv_bfloat162 hp; hp.x = h0; hp.y = h1;
                    __nv_bfloat162 lp; lp.x = l0; lp.y = l1;
                    size_t o = (size_t)rowg * Npad + colg;
                    *(__nv_bfloat162*)(Chi + o) = hp;
                    *(__nv_bfloat162*)(Clo + o) = lp;
                } else {
                    if (colg < Nreal)     Cf[(size_t)rowg * ldc + colg]     = v0;
                    if (colg + 1 < Nreal) Cf[(size_t)rowg * ldc + colg + 1] = v1;
                }
            }
        }
    }
}

// ---------------- attention (split output) ------------------
__global__ __launch_bounds__(256) void attn_kernel() {
    int b = blockIdx.x / Hn;
    int h = blockIdx.x - b * Hn;
    int t = threadIdx.x;

    __shared__ float4 ks[Tn];
    __shared__ float4 vs[Tn];

    int base = (b * Tn + t) * 72;
    ks[t] = *(const float4*)&g_qkv[base + 24 + h * 4];
    vs[t] = *(const float4*)&g_qkv[base + 48 + h * 4];
    __syncthreads();

    float4 q = *(const float4*)&g_qkv[base + h * 4];
    const float scale = 0.05103103630798287f;  // 1/sqrt(384)
    q.x *= scale; q.y *= scale; q.z *= scale; q.w *= scale;

    float m = -1e30f, l = 0.f;
    float ax = 0.f, ay = 0.f, az = 0.f, aw = 0.f;
    for (int s = 0; s <= t; s++) {
        float4 k = ks[s];
        float sc = q.x * k.x + q.y * k.y + q.z * k.z + q.w * k.w;
        float mn = fmaxf(m, sc);
        float corr = __expf(m - mn);
        float p = __expf(sc - mn);
        l = l * corr + p;
        float4 v = vs[s];
        ax = ax * corr + p * v.x;
        ay = ay * corr + p * v.y;
        az = az * corr + p * v.z;
        aw = aw * corr + p * v.w;
        m = mn;
    }
    float inv = 1.f / l;
    float o[4] = { ax * inv, ay * inv, az * inv, aw * inv };
    size_t rb = (size_t)(b * Tn + t) * 64;
#pragma unroll
    for (int d = 0; d < 4; d++) {
        __nv_bfloat16 hi, lo; split2(o[d], hi, lo);
        g_atth[rb + h * 4 + d] = hi;
        g_attl[rb + h * 4 + d] = lo;
    }
    if (h == 0) {
        __nv_bfloat16 z = __float2bfloat16_rn(0.f);
        for (int cpad = 24; cpad < 64; cpad++) {
            g_atth[rb + cpad] = z;
            g_attl[rb + cpad] = z;
        }
    }
}

// ---------------- per-row NLL from logits in out -----------------------------
__global__ __launch_bounds__(256) void rowloss_kernel(const float* __restrict__ out,
                                                      const int* __restrict__ targets) {
    int row = blockIdx.x * 8 + (threadIdx.x >> 5);
    int lane = threadIdx.x & 31;
    const float* lg = out + (size_t)row * Vn;
    float v0 = lg[lane];
    float v1 = lg[lane + 32];
    float v2 = (lane == 0) ? lg[64] : -1e30f;
    float mx = fmaxf(fmaxf(v0, v1), v2);
#pragma unroll
    for (int o = 16; o; o >>= 1) mx = fmaxf(mx, __shfl_xor_sync(0xffffffffu, mx, o));
    float se = __expf(v0 - mx) + __expf(v1 - mx) + ((lane == 0) ? __expf(v2 - mx) : 0.f);
#pragma unroll
    for (int o = 16; o; o >>= 1) se += __shfl_xor_sync(0xffffffffu, se, o);
    if (lane == 0) {
        int tg = targets[row];
        g_rowloss[row] = -(lg[tg] - mx - __logf(se));
    }
}

__global__ __launch_bounds__(256) void loss_reduce_kernel(float* __restrict__ out,
                                                          int out_size) {
    __shared__ float sm[256];
    int tid = threadIdx.x;
    float s = 0.f;
    for (int i = tid; i < BTn; i += 256) s += g_rowloss[i];
    sm[tid] = s;
    __syncthreads();
    for (int st = 128; st > 0; st >>= 1) {
        if (tid < st) sm[tid] += sm[tid + st];
        __syncthreads();
    }
    float loss = sm[0] * (1.f / BTn);
    for (int i = BTn * Vn + tid; i < out_size; i += 256) out[i] = loss;
}

// ---------------------------------------------------------------------------
extern "C" void kernel_launch(void* const* d_in, const int* in_sizes, int n_in,
                              void* d_out, int out_size) {
    const int*   idx     = (const int*)d_in[0];
    const int*   targets = (const int*)d_in[1];
    const float* tok     = (const float*)d_in[2];
    const float* pos     = (const float*)d_in[3];
    const float* Wq      = (const float*)d_in[4];
    const float* Wk      = (const float*)d_in[5];
    const float* Wv      = (const float*)d_in[6];
    const float* Wproj   = (const float*)d_in[7];
    const float* bproj   = (const float*)d_in[8];
    const float* W1      = (const float*)d_in[9];
    const float* b1      = (const float*)d_in[10];
    const float* W2      = (const float*)d_in[11];
    const float* b2      = (const float*)d_in[12];
    const float* Wlm     = (const float*)d_in[13];
    const float* blm     = (const float*)d_in[14];
    float* out = (float*)d_out;

    void *pxh, *pxl, *pqkvw, *pbqh, *pbql, *pqkv, *path, *patl, *pbph, *pbpl;
    void *px2h, *px2l, *pb1h, *pb1l, *phh, *phl, *pb2h, *pb2l, *px3h, *px3l, *pblh, *pbll;
    cudaGetSymbolAddress(&pxh, g_xhi);   cudaGetSymbolAddress(&pxl, g_xlo);
    cudaGetSymbolAddress(&pqkvw, g_qkvw);
    cudaGetSymbolAddress(&pbqh, g_bqkvh); cudaGetSymbolAddress(&pbql, g_bqkvl);
    cudaGetSymbolAddress(&pqkv, g_qkv);
    cudaGetSymbolAddress(&path, g_atth);  cudaGetSymbolAddress(&patl, g_attl);
    cudaGetSymbolAddress(&pbph, g_bprojh); cudaGetSymbolAddress(&pbpl, g_bprojl);
    cudaGetSymbolAddress(&px2h, g_x2h);   cudaGetSymbolAddress(&px2l, g_x2l);
    cudaGetSymbolAddress(&pb1h, g_b1h);   cudaGetSymbolAddress(&pb1l, g_b1l);
    cudaGetSymbolAddress(&phh, g_hh);     cudaGetSymbolAddress(&phl, g_hl);
    cudaGetSymbolAddress(&pb2h, g_b2h);   cudaGetSymbolAddress(&pb2l, g_b2l);
    cudaGetSymbolAddress(&px3h, g_x3h);   cudaGetSymbolAddress(&px3l, g_x3l);
    cudaGetSymbolAddress(&pblh, g_blmh);  cudaGetSymbolAddress(&pbll, g_blml);

    const int SMEM = 2 * STAGE_B;  // 81920
    cudaFuncSetAttribute(tc_gemm<false,false,false>, cudaFuncAttributeMaxDynamicSharedMemorySize, SMEM);
    cudaFuncSetAttribute(tc_gemm<false,true, false>, cudaFuncAttributeMaxDynamicSharedMemorySize, SMEM);
    cudaFuncSetAttribute(tc_gemm<false,true, true >, cudaFuncAttributeMaxDynamicSharedMemorySize, SMEM);
    cudaFuncSetAttribute(tc_gemm<true, true, true >, cudaFuncAttributeMaxDynamicSharedMemorySize, SMEM);

    pack_qkvw_kernel<<<(Cn*72 + 255)/256, 256>>>(Wq, Wk, Wv);
    pack_split_b<<<(128*Cn + 255)/256, 256>>>((const float*)pqkvw, 72, 72, Cn, 128, Cn,
                                              (__nv_bfloat16*)pbqh, (__nv_bfloat16*)pbql);
    pack_split_b<<<(Cn*64 + 255)/256, 256>>>(Wproj, Cn, Cn, 24, Cn, 64,
                                             (__nv_bfloat16*)pbph, (__nv_bfloat16*)pbpl);
    pack_split_b<<<(Fn*Cn + 255)/256, 256>>>(W1, Fn, Fn, Cn, Fn, Cn,
                                             (__nv_bfloat16*)pb1h, (__nv_bfloat16*)pb1l);
    pack_split_b<<<(Cn*Fn + 255)/256, 256>>>(W2, Cn, Cn, Fn, Cn, Fn,
                                             (__nv_bfloat16*)pb2h, (__nv_bfloat16*)pb2l);
    pack_split_b<<<(128*Cn + 255)/256, 256>>>(Wlm, Vn, Vn, Cn, 128, Cn,
                                              (__nv_bfloat16*)pblh, (__nv_bfloat16*)pbll);

    embed_kernel<<<(BTn*Cn + 255)/256, 256>>>(idx, tok, pos);

    // qkv: [BT,384] @ [384,72pad128] -> float g_qkv
    tc_gemm<false,false,false><<<dim3(1, BTn/128), 256, SMEM>>>(
        (const __nv_bfloat16*)pxh, (const __nv_bfloat16*)pxl, Cn,
        (const __nv_bfloat16*)pbqh, (const __nv_bfloat16*)pbql,
        nullptr, (float*)pqkv, 72, 72, nullptr, nullptr, 0);

    attn_kernel<<<128 * Hn, Tn>>>();

    // proj: [BT,64pad] @ [64,384] + bproj -> split x2
    tc_gemm<false,true,true><<<dim3(3, BTn/128), 256, SMEM>>>(
        (const __nv_bfloat16*)path, (const __nv_bfloat16*)patl, 64,
        (const __nv_bfloat16*)pbph, (const __nv_bfloat16*)pbpl,
        bproj, nullptr, 0, 0, (__nv_bfloat16*)px2h, (__nv_bfloat16*)px2l, Cn);

    // ffn1: relu([BT,384] @ [384,1536] + b1) -> split h
    tc_gemm<true,true,true><<<dim3(12, BTn/128), 256, SMEM>>>(
        (const __nv_bfloat16*)px2h, (const __nv_bfloat16*)px2l, Cn,
        (const __nv_bfloat16*)pb1h, (const __nv_bfloat16*)pb1l,
        b1, nullptr, 0, 0, (__nv_bfloat16*)phh, (__nv_bfloat16*)phl, Fn);

    // ffn2: [BT,1536] @ [1536,384] + b2 -> split x3
    tc_gemm<false,true,true><<<dim3(3, BTn/128), 256, SMEM>>>(
        (const __nv_bfloat16*)phh, (const __nv_bfloat16*)phl, Fn,
        (const __nv_bfloat16*)pb2h, (const __nv_bfloat16*)pb2l,
        b2, nullptr, 0, 0, (__nv_bfloat16*)px3h, (__nv_bfloat16*)px3l, Cn);

    // lm: [BT,384] @ [384,65pad128] + blm -> float logits into out
    tc_gemm<false,true,false><<<dim3(1, BTn/128), 256, SMEM>>>(
        (const __nv_bfloat16*)px3h, (const __nv_bfloat16*)px3l, Cn,
        (const __nv_bfloat16*)pblh, (const __nv_bfloat16*)pbll,
        blm, out, Vn, Vn, nullptr, nullptr, 0);

    rowloss_kernel<<<BTn/8, 256>>>(out, targets);
    loss_reduce_kernel<<<1, 256>>>(out, out_size);
}

// round 4
// speedup vs baseline: 2.2196x; 1.0585x over previous
#include <cuda_runtime.h>
#include <cuda_bf16.h>
#include <cstdint>

#define BTn 32768
#define Tn  256
#define Cn  384
#define Hn  6
#define Vn  65
#define Fn  1536

// ---------------- scratch (device globals; allocation-free rule) -----------
__device__ __nv_bfloat16 g_xhi[BTn*Cn], g_xlo[BTn*Cn];      // embeddings split
__device__ __nv_bfloat16 g_bqkvh[128*Cn], g_bqkvl[128*Cn];  // qkv B [Npad=128,K=384]
__device__ float         g_qkv[BTn*72];                     // qkv activations
__device__ __nv_bfloat16 g_atth[BTn*64], g_attl[BTn*64];    // attn out split, padded K=64
__device__ __nv_bfloat16 g_bprojh[Cn*64], g_bprojl[Cn*64];  // proj B [384,Kpad=64]
__device__ __nv_bfloat16 g_x2h[BTn*Cn], g_x2l[BTn*Cn];      // proj out split
__device__ __nv_bfloat16 g_b1h[Fn*Cn], g_b1l[Fn*Cn];        // W1^T split [1536,384]
__device__ __nv_bfloat16 g_hh[BTn*Fn], g_hl[BTn*Fn];        // ffn hidden split
__device__ __nv_bfloat16 g_b2h[Cn*Fn], g_b2l[Cn*Fn];        // W2^T split [384,1536]
__device__ __nv_bfloat16 g_x3h[BTn*Cn], g_x3l[BTn*Cn];      // ffn out split
__device__ __nv_bfloat16 g_blmh[128*Cn], g_blml[128*Cn];    // Wlm^T split [Npad=128,384]
__device__ float         g_rowloss[BTn];

// ---------------- helpers ----------------------------------------------
__device__ __forceinline__ uint32_t smem_u32(const void* p) {
    return (uint32_t)__cvta_generic_to_shared(p);
}

__device__ __forceinline__ void cp16(uint32_t dst, const void* src) {
    asm volatile("cp.async.cg.shared.global [%0], [%1], 16;" :: "r"(dst), "l"(src));
}
#define CP_COMMIT() asm volatile("cp.async.commit_group;" ::: "memory")
#define CP_WAIT(n)  asm volatile("cp.async.wait_group %0;" :: "n"(n) : "memory")

__device__ __forceinline__ void mma_bf16(float* d, const uint32_t* a, uint32_t b0, uint32_t b1) {
    asm volatile(
        "mma.sync.aligned.m16n8k16.row.col.f32.bf16.bf16.f32 "
        "{%0,%1,%2,%3}, {%4,%5,%6,%7}, {%8,%9}, {%0,%1,%2,%3};"
        : "+f"(d[0]), "+f"(d[1]), "+f"(d[2]), "+f"(d[3])
        : "r"(a[0]), "r"(a[1]), "r"(a[2]), "r"(a[3]), "r"(b0), "r"(b1));
}

__device__ __forceinline__ void ldm_x4(uint32_t* r, uint32_t addr) {
    asm volatile("ldmatrix.sync.aligned.m8n8.x4.shared.b16 {%0,%1,%2,%3}, [%4];"
        : "=r"(r[0]), "=r"(r[1]), "=r"(r[2]), "=r"(r[3]) : "r"(addr));
}

__device__ __forceinline__ void split2(float v, __nv_bfloat16& h, __nv_bfloat16& l) {
    h = __float2bfloat16_rn(v);
    l = __float2bfloat16_rn(v - __bfloat162float(h));
}

// ---------------- fused weight pack --------------------------------------
// Segments (all dst [Npad][Kpad] K-major hi/lo):
// 0: qkv   Npad=128 (72 real, from Wq/Wk/Wv [H,C,D]), Kpad=384
// 1: proj  Npad=384, Kpad=64 (24 real) from Wproj [24,384]
// 2: W1^T  Npad=1536, Kpad=384 from W1 [384,1536]
// 3: W2^T  Npad=384, Kpad=1536 from W2 [1536,384]
// 4: lm    Npad=128 (65 real), Kpad=384 from Wlm [384,65]
__global__ void pack_all(const float* __restrict__ Wq, const float* __restrict__ Wk,
                         const float* __restrict__ Wv, const float* __restrict__ Wproj,
                         const float* __restrict__ W1, const float* __restrict__ W2,
                         const float* __restrict__ Wlm) {
    const int S0 = 128*Cn, S1 = Cn*64, S2 = Fn*Cn, S3 = Cn*Fn, S4 = 128*Cn;
    int i = blockIdx.x * blockDim.x + threadIdx.x;
    int total = S0 + S1 + S2 + S3 + S4;
    if (i >= total) return;
    float v; __nv_bfloat16 *hi, *lo; int o;
    if (i < S0) {
        o = i; int n = o / Cn, k = o - n * Cn;
        if (n < 72) {
            int g = n / 24, rem = n - g * 24, h = rem >> 2, d = rem & 3;
            const float* W = (g == 0) ? Wq : (g == 1) ? Wk : Wv;
            v = W[(h * Cn + k) * 4 + d];
        } else v = 0.f;
        hi = g_bqkvh; lo = g_bqkvl;
    } else if (i < S0 + S1) {
        o = i - S0; int n = o / 64, k = o - n * 64;
        v = (k < 24) ? Wproj[k * Cn + n] : 0.f;
        hi = g_bprojh; lo = g_bprojl;
    } else if (i < S0 + S1 + S2) {
        o = i - S0 - S1; int n = o / Cn, k = o - n * Cn;
        v = W1[(size_t)k * Fn + n];
        hi = g_b1h; lo = g_b1l;
    } else if (i < S0 + S1 + S2 + S3) {
        o = i - S0 - S1 - S2; int n = o / Fn, k = o - n * Fn;
        v = W2[(size_t)k * Cn + n];
        hi = g_b2h; lo = g_b2l;
    } else {
        o = i - S0 - S1 - S2 - S3; int n = o / Cn, k = o - n * Cn;
        v = (n < Vn) ? Wlm[k * Vn + n] : 0.f;
        hi = g_blmh; lo = g_blml;
    }
    __nv_bfloat16 h, l; split2(v, h, l);
    hi[o] = h; lo[o] = l;
}

__global__ void embed_kernel(const int* __restrict__ idx,
                             const float* __restrict__ tok,
                             const float* __restrict__ pos) {
    int i = blockIdx.x * blockDim.x + threadIdx.x;
    if (i >= BTn * Cn) return;
    int bt = i / Cn, c = i - bt * Cn;
    int t = bt & (Tn - 1);
    float v = tok[__ldg(&idx[bt]) * Cn + c] + pos[t * Cn + c];
    __nv_bfloat16 h, l; split2(v, h, l);
    g_xhi[i] = h; g_xlo[i] = l;
}

// ---------------- mma.sync split-bf16 GEMM, ldmatrix fragments --------------
// C[M,N] = A[M,K] @ B^T. 128x128 tile, BK=32, 8 warps (4M x 2N), warp 32x64.
#define BKP 40                   // padded smem row (bf16): 80 B, conflict-free
#define ROWB (BKP * 2)           // 80
#define TILE_B (128 * ROWB)      // 10240
#define STAGE_B (4 * TILE_B)     // 40960

template <bool RELU, bool HASBIAS, bool SPLITOUT>
__global__ __launch_bounds__(256, 2) void tc_gemm(
    const __nv_bfloat16* __restrict__ Ahi, const __nv_bfloat16* __restrict__ Alo, int Kpad,
    const __nv_bfloat16* __restrict__ Bhi, const __nv_bfloat16* __restrict__ Blo,
    const float* __restrict__ bias,
    float* __restrict__ Cf, int ldc, int Nreal,
    __nv_bfloat16* __restrict__ Chi, __nv_bfloat16* __restrict__ Clo, int Npad)
{
    extern __shared__ char smem[];
    const int tid  = threadIdx.x;
    const int lane = tid & 31, wid = tid >> 5;
    const int wm = wid & 3, wn = wid >> 2;
    const int m0 = blockIdx.y * 128, n0 = blockIdx.x * 128;

    const __nv_bfloat16* gsrc[4] = {
        Ahi + (size_t)m0 * Kpad, Alo + (size_t)m0 * Kpad,
        Bhi + (size_t)n0 * Kpad, Blo + (size_t)n0 * Kpad };

    const int nk = Kpad / 32;
    const uint32_t sbase = smem_u32(smem);

    auto load_stage = [&](int stage, int c) {
        uint32_t dst0 = sbase + stage * STAGE_B;
        int kc0 = c * 32;
#pragma unroll
        for (int tile = 0; tile < 4; tile++) {
            const __nv_bfloat16* g = gsrc[tile] + kc0;
#pragma unroll
            for (int t = 0; t < 2; t++) {
                int j = tid + t * 256;
                int row = j >> 2, seg = j & 3;
                cp16(dst0 + tile * TILE_B + row * ROWB + seg * 16,
                     g + (size_t)row * Kpad + seg * 8);
            }
        }
        CP_COMMIT();
    };

    float acc[2][8][4];
#pragma unroll
    for (int mi = 0; mi < 2; mi++)
#pragma unroll
        for (int nj = 0; nj < 8; nj++)
#pragma unroll
            for (int q = 0; q < 4; q++) acc[mi][nj][q] = 0.f;

    load_stage(0, 0);

    // ldmatrix per-lane address components: row = lane&15, k-half = lane>>4
    const uint32_t laneOff = (uint32_t)((lane & 15) * ROWB + (lane >> 4) * 16);
    const uint32_t Aoff0 = (uint32_t)((wm * 32) * ROWB) + laneOff;            // mi=0
    const uint32_t Aoff1 = Aoff0 + 16 * ROWB;                                  // mi=1
    const uint32_t Boff0 = (uint32_t)((wn * 64) * ROWB) + laneOff;

    const int r8 = lane >> 2, q4 = lane & 3;

    for (int c = 0; c < nk; c++) {
        if (c + 1 < nk) { load_stage((c + 1) & 1, c + 1); CP_WAIT(1); }
        else            { CP_WAIT(0); }
        __syncthreads();

        const uint32_t st = sbase + (c & 1) * STAGE_B;
        const uint32_t stAh = st, stAl = st + TILE_B;
        const uint32_t stBh = st + 2 * TILE_B, stBl = st + 3 * TILE_B;

#pragma unroll
        for (int step = 0; step < 2; step++) {
            const uint32_t ko = step * 32;
            uint32_t a_h[2][4], a_l[2][4];
            ldm_x4(a_h[0], stAh + Aoff0 + ko);
            ldm_x4(a_h[1], stAh + Aoff1 + ko);
            ldm_x4(a_l[0], stAl + Aoff0 + ko);
            ldm_x4(a_l[1], stAl + Aoff1 + ko);
#pragma unroll
            for (int p = 0; p < 4; p++) {
                uint32_t b_h[4], b_l[4];
                const uint32_t bo = Boff0 + (uint32_t)(p * 16 * ROWB) + ko;
                ldm_x4(b_h, stBh + bo);
                ldm_x4(b_l, stBl + bo);
                // x4 regs: {n0-7,k0-7},{n8-15,k0-7},{n0-7,k8-15},{n8-15,k8-15}
#pragma unroll
                for (int mi = 0; mi < 2; mi++) {
                    mma_bf16(acc[mi][2*p],   a_h[mi], b_h[0], b_h[2]);
                    mma_bf16(acc[mi][2*p],   a_h[mi], b_l[0], b_l[2]);
                    mma_bf16(acc[mi][2*p],   a_l[mi], b_h[0], b_h[2]);
                    mma_bf16(acc[mi][2*p+1], a_h[mi], b_h[1], b_h[3]);
                    mma_bf16(acc[mi][2*p+1], a_h[mi], b_l[1], b_l[3]);
                    mma_bf16(acc[mi][2*p+1], a_l[mi], b_h[1], b_h[3]);
                }
            }
        }
        __syncthreads();
    }

    // ---- epilogue ----
#pragma unroll
    for (int mi = 0; mi < 2; mi++) {
#pragma unroll
        for (int nj = 0; nj < 8; nj++) {
            int colg = n0 + wn * 64 + nj * 8 + q4 * 2;
#pragma unroll
            for (int half = 0; half < 2; half++) {
                int rowg = m0 + wm * 32 + mi * 16 + r8 + half * 8;
                float v0 = acc[mi][nj][half * 2 + 0];
                float v1 = acc[mi][nj][half * 2 + 1];
                if (HASBIAS) { v0 += bias[colg]; v1 += bias[colg + 1]; }
                if (RELU) { v0 = fmaxf(v0, 0.f); v1 = fmaxf(v1, 0.f); }
                if (SPLITOUT) {
                    __nv_bfloat16 h0, l0, h1, l1;
                    split2(v0, h0, l0); split2(v1, h1, l1);
                    __nv_bfloat162 hp; hp.x = h0; hp.y = h1;
                    __nv_bfloat162 lp; lp.x = l0; lp.y = l1;
                    size_t o = (size_t)rowg * Npad + colg;
                    *(__nv_bfloat162*)(Chi + o) = hp;
                    *(__nv_bfloat162*)(Clo + o) = lp;
                } else {
                    if (colg < Nreal)     Cf[(size_t)rowg * ldc + colg]     = v0;
                    if (colg + 1 < Nreal) Cf[(size_t)rowg * ldc + colg + 1] = v1;
                }
            }
        }
    }
}

// ---------------- attention (split output) ------------------
__global__ __launch_bounds__(256) void attn_kernel() {
    int b = blockIdx.x / Hn;
    int h = blockIdx.x - b * Hn;
    int t = threadIdx.x;

    __shared__ float4 ks[Tn];
    __shared__ float4 vs[Tn];

    int base = (b * Tn + t) * 72;
    ks[t] = *(const float4*)&g_qkv[base + 24 + h * 4];
    vs[t] = *(const float4*)&g_qkv[base + 48 + h * 4];
    __syncthreads();

    float4 q = *(const float4*)&g_qkv[base + h * 4];
    const float scale = 0.05103103630798287f;  // 1/sqrt(384)
    q.x *= scale; q.y *= scale; q.z *= scale; q.w *= scale;

    float m = -1e30f, l = 0.f;
    float ax = 0.f, ay = 0.f, az = 0.f, aw = 0.f;
    for (int s = 0; s <= t; s++) {
        float4 k = ks[s];
        float sc = q.x * k.x + q.y * k.y + q.z * k.z + q.w * k.w;
        float mn = fmaxf(m, sc);
        float corr = __expf(m - mn);
        float p = __expf(sc - mn);
        l = l * corr + p;
        float4 v = vs[s];
        ax = ax * corr + p * v.x;
        ay = ay * corr + p * v.y;
        az = az * corr + p * v.z;
        aw = aw * corr + p * v.w;
        m = mn;
    }
    float inv = 1.f / l;
    float o[4] = { ax * inv, ay * inv, az * inv, aw * inv };
    size_t rb = (size_t)(b * Tn + t) * 64;
#pragma unroll
    for (int d = 0; d < 4; d++) {
        __nv_bfloat16 hi, lo; split2(o[d], hi, lo);
        g_atth[rb + h * 4 + d] = hi;
        g_attl[rb + h * 4 + d] = lo;
    }
    if (h == 0) {
        __nv_bfloat16 z = __float2bfloat16_rn(0.f);
        for (int cpad = 24; cpad < 64; cpad++) {
            g_atth[rb + cpad] = z;
            g_attl[rb + cpad] = z;
        }
    }
}

// ---------------- per-row NLL from logits in out -----------------------------
__global__ __launch_bounds__(256) void rowloss_kernel(const float* __restrict__ out,
                                                      const int* __restrict__ targets) {
    int row = blockIdx.x * 8 + (threadIdx.x >> 5);
    int lane = threadIdx.x & 31;
    const float* lg = out + (size_t)row * Vn;
    float v0 = lg[lane];
    float v1 = lg[lane + 32];
    float v2 = (lane == 0) ? lg[64] : -1e30f;
    float mx = fmaxf(fmaxf(v0, v1), v2);
#pragma unroll
    for (int o = 16; o; o >>= 1) mx = fmaxf(mx, __shfl_xor_sync(0xffffffffu, mx, o));
    float se = __expf(v0 - mx) + __expf(v1 - mx) + ((lane == 0) ? __expf(v2 - mx) : 0.f);
#pragma unroll
    for (int o = 16; o; o >>= 1) se += __shfl_xor_sync(0xffffffffu, se, o);
    if (lane == 0) {
        int tg = targets[row];
        g_rowloss[row] = -(lg[tg] - mx - __logf(se));
    }
}

__global__ __launch_bounds__(256) void loss_reduce_kernel(float* __restrict__ out,
                                                          int out_size) {
    __shared__ float sm[256];
    int tid = threadIdx.x;
    float s = 0.f;
    for (int i = tid; i < BTn; i += 256) s += g_rowloss[i];
    sm[tid] = s;
    __syncthreads();
    for (int st = 128; st > 0; st >>= 1) {
        if (tid < st) sm[tid] += sm[tid + st];
        __syncthreads();
    }
    float loss = sm[0] * (1.f / BTn);
    for (int i = BTn * Vn + tid; i < out_size; i += 256) out[i] = loss;
}

// ---------------------------------------------------------------------------
extern "C" void kernel_launch(void* const* d_in, const int* in_sizes, int n_in,
                              void* d_out, int out_size) {
    const int*   idx     = (const int*)d_in[0];
    const int*   targets = (const int*)d_in[1];
    const float* tok     = (const float*)d_in[2];
    const float* pos     = (const float*)d_in[3];
    const float* Wq      = (const float*)d_in[4];
    const float* Wk      = (const float*)d_in[5];
    const float* Wv      = (const float*)d_in[6];
    const float* Wproj   = (const float*)d_in[7];
    const float* bproj   = (const float*)d_in[8];
    const float* W1      = (const float*)d_in[9];
    const float* b1      = (const float*)d_in[10];
    const float* W2      = (const float*)d_in[11];
    const float* b2      = (const float*)d_in[12];
    const float* Wlm     = (const float*)d_in[13];
    const float* blm     = (const float*)d_in[14];
    float* out = (float*)d_out;

    void *pxh, *pxl, *pbqh, *pbql, *pqkv, *path, *patl, *pbph, *pbpl;
    void *px2h, *px2l, *pb1h, *pb1l, *phh, *phl, *pb2h, *pb2l, *px3h, *px3l, *pblh, *pbll;
    cudaGetSymbolAddress(&pxh, g_xhi);   cudaGetSymbolAddress(&pxl, g_xlo);
    cudaGetSymbolAddress(&pbqh, g_bqkvh); cudaGetSymbolAddress(&pbql, g_bqkvl);
    cudaGetSymbolAddress(&pqkv, g_qkv);
    cudaGetSymbolAddress(&path, g_atth);  cudaGetSymbolAddress(&patl, g_attl);
    cudaGetSymbolAddress(&pbph, g_bprojh); cudaGetSymbolAddress(&pbpl, g_bprojl);
    cudaGetSymbolAddress(&px2h, g_x2h);   cudaGetSymbolAddress(&px2l, g_x2l);
    cudaGetSymbolAddress(&pb1h, g_b1h);   cudaGetSymbolAddress(&pb1l, g_b1l);
    cudaGetSymbolAddress(&phh, g_hh);     cudaGetSymbolAddress(&phl, g_hl);
    cudaGetSymbolAddress(&pb2h, g_b2h);   cudaGetSymbolAddress(&pb2l, g_b2l);
    cudaGetSymbolAddress(&px3h, g_x3h);   cudaGetSymbolAddress(&px3l, g_x3l);
    cudaGetSymbolAddress(&pblh, g_blmh);  cudaGetSymbolAddress(&pbll, g_blml);

    const int SMEM = 2 * STAGE_B;  // 81920
    cudaFuncSetAttribute(tc_gemm<false,false,false>, cudaFuncAttributeMaxDynamicSharedMemorySize, SMEM);
    cudaFuncSetAttribute(tc_gemm<false,true, false>, cudaFuncAttributeMaxDynamicSharedMemorySize, SMEM);
    cudaFuncSetAttribute(tc_gemm<false,true, true >, cudaFuncAttributeMaxDynamicSharedMemorySize, SMEM);
    cudaFuncSetAttribute(tc_gemm<true, true, true >, cudaFuncAttributeMaxDynamicSharedMemorySize, SMEM);

    {
        const int total = 128*Cn + Cn*64 + Fn*Cn + Cn*Fn + 128*Cn;
        pack_all<<<(total + 255)/256, 256>>>(Wq, Wk, Wv, Wproj, W1, W2, Wlm);   // launch 1
    }
    embed_kernel<<<(BTn*Cn + 255)/256, 256>>>(idx, tok, pos);                   // launch 2

    // qkv: [BT,384] @ [384,72pad128] -> float g_qkv                            // launch 3
    tc_gemm<false,false,false><<<dim3(1, BTn/128), 256, SMEM>>>(
        (const __nv_bfloat16*)pxh, (const __nv_bfloat16*)pxl, Cn,
        (const __nv_bfloat16*)pbqh, (const __nv_bfloat16*)pbql,
        nullptr, (float*)pqkv, 72, 72, nullptr, nullptr, 0);

    attn_kernel<<<128 * Hn, Tn>>>();                                            // launch 4

    // proj: [BT,64pad] @ [64,384] + bproj -> split x2                          // launch 5
    tc_gemm<false,true,true><<<dim3(3, BTn/128), 256, SMEM>>>(
        (const __nv_bfloat16*)path, (const __nv_bfloat16*)patl, 64,
        (const __nv_bfloat16*)pbph, (const __nv_bfloat16*)pbpl,
        bproj, nullptr, 0, 0, (__nv_bfloat16*)px2h, (__nv_bfloat16*)px2l, Cn);

    // ffn1: relu([BT,384] @ [384,1536] + b1) -> split h                        // launch 6 (ncu slot)
    tc_gemm<true,true,true><<<dim3(12, BTn/128), 256, SMEM>>>(
        (const __nv_bfloat16*)px2h, (const __nv_bfloat16*)px2l, Cn,
        (const __nv_bfloat16*)pb1h, (const __nv_bfloat16*)pb1l,
        b1, nullptr, 0, 0, (__nv_bfloat16*)phh, (__nv_bfloat16*)phl, Fn);

    // ffn2: [BT,1536] @ [1536,384] + b2 -> split x3
    tc_gemm<false,true,true><<<dim3(3, BTn/128), 256, SMEM>>>(
        (const __nv_bfloat16*)phh, (const __nv_bfloat16*)phl, Fn,
        (const __nv_bfloat16*)pb2h, (const __nv_bfloat16*)pb2l,
        b2, nullptr, 0, 0, (__nv_bfloat16*)px3h, (__nv_bfloat16*)px3l, Cn);

    // lm: [BT,384] @ [384,65pad128] + blm -> float logits into out
    tc_gemm<false,true,false><<<dim3(1, BTn/128), 256, SMEM>>>(
        (const __nv_bfloat16*)px3h, (const __nv_bfloat16*)px3l, Cn,
        (const __nv_bfloat16*)pblh, (const __nv_bfloat16*)pbll,
        blm, out, Vn, Vn, nullptr, nullptr, 0);

    rowloss_kernel<<<BTn/8, 256>>>(out, targets);
    loss_reduce_kernel<<<1, 256>>>(out, out_size);
}